// round 14
// baseline (speedup 1.0000x reference)
#include <cuda_runtime.h>
#include <stdint.h>

#define NB 32
#define HH 512
#define WW 512
#define WPR 16     // 512 bits = 16 uint32 words per row
#define OWNR 14    // rows owned per k2 warp item
#define NI 37      // items per (batch, dir): ceil(512/14)
#define NITEM (NB * 2 * NI)   // 2368
#define K2BLK (NITEM / 8)     // 296 blocks

__device__ uint32_t g_pmask[NB][HH][WPR];
__device__ uint32_t g_gmask[NB][HH][WPR];
__device__ uint32_t g_pe[NB][HH][WPR];
__device__ uint32_t g_pm[NB][HH][WPR];
__device__ uint32_t g_pj[NB][HH][WPR];
// k1 per-block partials: S_p, S_pg, pec, pmc, pjc, N_p, N_g   (16 blocks/batch)
__device__ float g_part[NB][16][7];
// k2 structural per item: gec, gmc, gjc, Ie, Im, Ij
__device__ unsigned g_str[NB][NI][6];
// k2 medial per item
__device__ unsigned g_med[NB][2][NI];
__device__ unsigned g_ticket = 0;

struct Raw { float4 c; float l, r; };

__device__ __forceinline__ Raw load_raw(const float* __restrict__ img, size_t base,
                                        int r, int x0, int lane) {
    Raw o;
    if ((unsigned)r < HH) {
        const float* rp = img + base + (size_t)r * WW;
        o.c = __ldg((const float4*)rp + (x0 >> 2));
        o.l = 0.f; o.r = 0.f;
        if (lane == 0 && x0 > 0) o.l = __ldg(rp + x0 - 1);
        if (lane == 31 && x0 + 4 < WW) o.r = __ldg(rp + x0 + 4);
    } else {
        o.c = make_float4(0.f, 0.f, 0.f, 0.f);
        o.l = 0.f; o.r = 0.f;
    }
    return o;
}

__device__ __forceinline__ float4 make_h(const Raw& a, int lane) {
    float left  = __shfl_up_sync(0xFFFFFFFFu, a.c.w, 1);
    float right = __shfl_down_sync(0xFFFFFFFFu, a.c.x, 1);
    if (lane == 0)  left = a.l;
    if (lane == 31) right = a.r;
    float4 h;
    h.x = left  + a.c.x + a.c.y;
    h.y = a.c.x + a.c.y + a.c.z;
    h.z = a.c.y + a.c.z + a.c.w;
    h.w = a.c.z + a.c.w + right;
    return h;
}

// 512 blocks = (batch, half 0..1, row-chunk 0..7), 256 thr = 8 warps.
// Warp owns 8 rows x 256 cols (two 128-col substrips) -> 8 independent
// LDG.128 in flight per row iteration (doubled MLP vs single substrip).
__global__ void __launch_bounds__(256) k1_pixel(const float* __restrict__ pred,
                                                const float* __restrict__ gt) {
    const int tid = threadIdx.x, lane = tid & 31, w8 = tid >> 5;
    const int blk = blockIdx.x;
    const int b = blk >> 4, s = (blk >> 3) & 1, c = blk & 7;
    const int xA = s * 256 + lane * 4;
    const int xB = xA + 128;
    const int r0 = c * 64 + w8 * 8;
    const size_t base = (size_t)b * (HH * WW);

    float4 php[2], phc[2], pcc[2], gcur[2];
    Raw prn[2];
    {
        Raw pm_[2], p0_[2];
        pm_[0] = load_raw(pred, base, r0 - 1, xA, lane);
        pm_[1] = load_raw(pred, base, r0 - 1, xB, lane);
        p0_[0] = load_raw(pred, base, r0,     xA, lane);
        p0_[1] = load_raw(pred, base, r0,     xB, lane);
        prn[0] = load_raw(pred, base, r0 + 1, xA, lane);
        prn[1] = load_raw(pred, base, r0 + 1, xB, lane);
        gcur[0] = __ldg((const float4*)(gt + base + (size_t)r0 * WW + xA));
        gcur[1] = __ldg((const float4*)(gt + base + (size_t)r0 * WW + xB));
#pragma unroll
        for (int u = 0; u < 2; u++) {
            php[u] = make_h(pm_[u], lane);
            phc[u] = make_h(p0_[u], lane);
            pcc[u] = p0_[u].c;
        }
    }

    float Sp = 0.f, Spg = 0.f;
    unsigned pec = 0, pmc = 0, pjc = 0, cP = 0, cG = 0;

    for (int i = 0; i < 8; i++) {
        const int r = r0 + i;
        // prefetch: 4 independent LDG.128 (pred r+2 x2, gt r+1 x2)
        Raw pr2[2];
        pr2[0] = load_raw(pred, base, r + 2, xA, lane);
        pr2[1] = load_raw(pred, base, r + 2, xB, lane);
        float4 gnx[2] = {make_float4(0.f, 0.f, 0.f, 0.f),
                         make_float4(0.f, 0.f, 0.f, 0.f)};
        if (r + 1 < HH) {
            gnx[0] = __ldg((const float4*)(gt + base + (size_t)(r + 1) * WW + xA));
            gnx[1] = __ldg((const float4*)(gt + base + (size_t)(r + 1) * WW + xB));
        }

#pragma unroll
        for (int u = 0; u < 2; u++) {
            float4 phn = make_h(prn[u], lane);
            const float pcv[4] = {pcc[u].x, pcc[u].y, pcc[u].z, pcc[u].w};
            const float gcv[4] = {gcur[u].x, gcur[u].y, gcur[u].z, gcur[u].w};
            const float nps[4] = {php[u].x + phc[u].x + phn.x,
                                  php[u].y + phc[u].y + phn.y,
                                  php[u].z + phc[u].z + phn.z,
                                  php[u].w + phc[u].w + phn.w};
            unsigned pn = 0, gn = 0, pen = 0, pmn = 0, pjn = 0;
#pragma unroll
            for (int j = 0; j < 4; j++) {
                const float pc = pcv[j], gc = gcv[j];
                const bool pon = pc > 0.5f;
                const bool gon = gc > 0.5f;
                const float np = nps[j] - pc;
                const bool pe = pon && (np == 1.0f);
                const bool pm = pon && (np == 2.0f);
                const bool pj = pon && (np > 2.0f);
                Sp += pc;
                Spg += gon ? pc : 0.f;
                pn |= (unsigned)pon << j;
                gn |= (unsigned)gon << j;
                pen |= (unsigned)pe << j;
                pmn |= (unsigned)pm << j;
                pjn |= (unsigned)pj << j;
            }
            cP += __popc(pn); cG += __popc(gn);
            pec += __popc(pen); pmc += __popc(pmn); pjc += __popc(pjn);

            const unsigned grpmask = 0xFFu << (lane & 24);
            const unsigned sh = (lane & 7) * 4;
            unsigned pw = __reduce_or_sync(grpmask, pn << sh);
            unsigned gw = __reduce_or_sync(grpmask, gn << sh);
            unsigned ew = __reduce_or_sync(grpmask, pen << sh);
            unsigned mw = __reduce_or_sync(grpmask, pmn << sh);
            unsigned jw = __reduce_or_sync(grpmask, pjn << sh);
            if ((lane & 7) == 0) {
                const int wi = s * 8 + u * 4 + (lane >> 3);
                g_pmask[b][r][wi] = pw;
                g_gmask[b][r][wi] = gw;
                g_pe[b][r][wi] = ew;
                g_pm[b][r][wi] = mw;
                g_pj[b][r][wi] = jw;
            }
            php[u] = phc[u]; phc[u] = phn; pcc[u] = prn[u].c;
            prn[u] = pr2[u]; gcur[u] = gnx[u];
        }
    }

    // block reduce 7 values -> unique g_part slot
    float v7[7] = {Sp, Spg, (float)pec, (float)pmc, (float)pjc, (float)cP, (float)cG};
    __shared__ float sm_red[8][7];
#pragma unroll
    for (int k = 0; k < 7; k++) {
        float v = v7[k];
#pragma unroll
        for (int off = 16; off > 0; off >>= 1)
            v += __shfl_down_sync(0xFFFFFFFFu, v, off);
        if (lane == 0) sm_red[w8][k] = v;
    }
    __syncthreads();
    if (w8 == 0) {
#pragma unroll
        for (int k = 0; k < 7; k++) {
            float v = (lane < 8) ? sm_red[lane][k] : 0.0f;
#pragma unroll
            for (int off = 4; off > 0; off >>= 1)
                v += __shfl_down_sync(0xFFFFFFFFu, v, off);
            if (lane == 0) g_part[b][s * 8 + c][k] = v;
        }
    }
}

__device__ __forceinline__ unsigned warp_red(unsigned v) {
#pragma unroll
    for (int off = 16; off > 0; off >>= 1)
        v += __shfl_down_sync(0xFFFFFFFFu, v, off);
    return v;
}

__device__ __forceinline__ void load_row8(const uint4* p, int r, bool ok, uint64_t* R) {
#pragma unroll
    for (int q = 0; q < 4; q++) {
        uint4 a = ok ? __ldg(p + r * 4 + q) : make_uint4(0, 0, 0, 0);
        R[q * 2 + 0] = (uint64_t)a.x | ((uint64_t)a.y << 32);
        R[q * 2 + 1] = (uint64_t)a.z | ((uint64_t)a.w << 32);
    }
}

// 296 blocks, 8 warps; ONE item per warp = (batch, dir, 14-row span).
// TRANSPOSED layout: lane = row (14 owned + 2*9 halo = 32), 8 uint64/lane.
// Horizontal dilation = register funnels (no SHFL); vertical = 16 independent
// 64-bit shuffles per iteration. Early exit exact. dir=0 also does gt
// structural classes via bit CSA. Last block folds everything.
__global__ void __launch_bounds__(256) k2_dilate(float* __restrict__ out) {
    const int tid = threadIdx.x, lane = tid & 31, wid = tid >> 5;
    const int it = blockIdx.x * 8 + wid;
    const int b = it / (2 * NI);
    const int rem = it % (2 * NI);
    const int dir = rem / NI;
    const int Wc = rem % NI;
    const int own0 = Wc * OWNR;
    const int ownend = (own0 + OWNR > HH) ? HH : own0 + OWNR;
    const int r = own0 - 9 + lane;
    const bool in = (unsigned)r < HH;
    const bool owned = (r >= own0) && (r < ownend);

    const uint4* refp = (dir == 0) ? (const uint4*)&g_gmask[b][0][0]
                                   : (const uint4*)&g_pmask[b][0][0];
    const uint4* tgp  = (dir == 0) ? (const uint4*)&g_pmask[b][0][0]
                                   : (const uint4*)&g_gmask[b][0][0];

    uint64_t R[8], tg[8];
    load_row8(refp, in ? r : 0, in, R);
    load_row8(tgp, owned ? r : 0, owned, tg);

    // ---- structural on gt (dir==0): bit-sliced 8-neighbor counter ----
    if (dir == 0) {
        uint64_t up[8], dn[8];
#pragma unroll
        for (int j = 0; j < 8; j++) {
            uint64_t u = __shfl_up_sync(0xFFFFFFFFu, R[j], 1);
            uint64_t d = __shfl_down_sync(0xFFFFFFFFu, R[j], 1);
            up[j] = (lane == 0) ? 0ull : u;
            dn[j] = (lane == 31) ? 0ull : d;
        }
        if (owned) {
            uint64_t pe8[8], pm8[8], pj8[8];
            load_row8((const uint4*)&g_pe[b][0][0], r, true, pe8);
            load_row8((const uint4*)&g_pm[b][0][0], r, true, pm8);
            load_row8((const uint4*)&g_pj[b][0][0], r, true, pj8);
            unsigned gec = 0, gmc = 0, gjc = 0, Ie = 0, Im = 0, Ij = 0;
#pragma unroll
            for (int j = 0; j < 8; j++) {
                uint64_t ul = (up[j] << 1) | (j > 0 ? up[j - 1] >> 63 : 0ull);
                uint64_t ur = (up[j] >> 1) | (j < 7 ? up[j + 1] << 63 : 0ull);
                uint64_t cl = (R[j] << 1)  | (j > 0 ? R[j - 1] >> 63 : 0ull);
                uint64_t cr = (R[j] >> 1)  | (j < 7 ? R[j + 1] << 63 : 0ull);
                uint64_t dl = (dn[j] << 1) | (j > 0 ? dn[j - 1] >> 63 : 0ull);
                uint64_t dr = (dn[j] >> 1) | (j < 7 ? dn[j + 1] << 63 : 0ull);
                uint64_t in8[8] = {ul, up[j], ur, cl, cr, dl, dn[j], dr};
                uint64_t c0 = 0, c1 = 0, ge4 = 0;
#pragma unroll
                for (int t = 0; t < 8; t++) {
                    uint64_t car = c0 & in8[t];
                    c0 ^= in8[t];
                    uint64_t car2 = c1 & car;
                    c1 ^= car;
                    ge4 |= car2;
                }
                uint64_t g = R[j];
                uint64_t geW = g & c0 & ~c1 & ~ge4;
                uint64_t gmW = g & ~c0 & c1 & ~ge4;
                uint64_t gjW = g & (ge4 | (c0 & c1));
                gec += __popcll(geW); gmc += __popcll(gmW); gjc += __popcll(gjW);
                Ie += __popcll(geW & pe8[j]);
                Im += __popcll(gmW & pm8[j]);
                Ij += __popcll(gjW & pj8[j]);
            }
            unsigned sr[6] = {gec, gmc, gjc, Ie, Im, Ij};
#pragma unroll
            for (int t = 0; t < 6; t++) {
                unsigned v = sr[t];
#pragma unroll
                for (int off = 16; off > 0; off >>= 1)
                    v += __shfl_down_sync(0xFFFFFFFFu, v, off);
                if (lane == 9) g_str[b][Wc][t] = v;   // lane 9 = first owned lane
            }
        } else {
            // unowned lanes still participate in the shuffles above; the
            // reductions below must include them with zero contribution
            unsigned z = 0;
#pragma unroll
            for (int t = 0; t < 6; t++) {
                unsigned v = z;
#pragma unroll
                for (int off = 16; off > 0; off >>= 1)
                    v += __shfl_down_sync(0xFFFFFFFFu, v, off);
                (void)v;
            }
        }
    }

    // ---- iterated square dilation, early exit ----
    unsigned acc = 0;
#pragma unroll 1
    for (int k = 1; k <= 9; k++) {
        uint64_t hz[8];
#pragma unroll
        for (int j = 0; j < 8; j++)
            hz[j] = R[j] | (R[j] << 1) | (R[j] >> 1)
                  | (j > 0 ? R[j - 1] >> 63 : 0ull)
                  | (j < 7 ? R[j + 1] << 63 : 0ull);
        uint64_t un = 0;
#pragma unroll
        for (int j = 0; j < 8; j++) {
            uint64_t u = __shfl_up_sync(0xFFFFFFFFu, hz[j], 1);
            uint64_t d = __shfl_down_sync(0xFFFFFFFFu, hz[j], 1);
            if (lane == 0)  u = 0ull;
            if (lane == 31) d = 0ull;
            uint64_t v = hz[j] | u | d;
            R[j] = v;
            uint64_t uc = tg[j] & ~v;   // tg==0 on unowned lanes
            un |= uc;
            acc += (unsigned)__popcll(uc);
        }
        if (!__any_sync(0xFFFFFFFFu, un != 0ull)) break;
    }
    {
        unsigned v = warp_red(acc);
        if (lane == 0) g_med[b][dir][Wc] = v;
    }

    // ---- ticket: last block computes the final scalar ----
    __shared__ bool isLast;
    __threadfence();
    __syncthreads();
    if (tid == 0) {
        unsigned old = atomicAdd(&g_ticket, 1u);
        isLast = (old == (unsigned)(gridDim.x - 1));
        if (isLast) __threadfence();
    }
    __syncthreads();
    if (!isLast) return;

    __shared__ float smf[32][8][15];
    {
        const int fb = tid >> 3, grp = tid & 7;
        float part[15];
#pragma unroll
        for (int k = 0; k < 15; k++) part[k] = 0.f;
#pragma unroll
        for (int q = 0; q < 2; q++) {
            int sc = grp * 2 + q;
#pragma unroll
            for (int k = 0; k < 7; k++) part[k] += g_part[fb][sc][k];
        }
#pragma unroll
        for (int q = 0; q < 5; q++) {
            int Wq = grp * 5 + q;
            if (Wq < NI) {
#pragma unroll
                for (int k = 0; k < 6; k++) part[7 + k] += (float)g_str[fb][Wq][k];
                part[13] += (float)g_med[fb][0][Wq];
                part[14] += (float)g_med[fb][1][Wq];
            }
        }
#pragma unroll
        for (int k = 0; k < 15; k++) smf[fb][grp][k] = part[k];
    }
    __syncthreads();
    if (tid < 32) {
        const int bb = tid;
        float a[15];
#pragma unroll
        for (int k = 0; k < 15; k++) {
            float v = 0.f;
#pragma unroll
            for (int g2 = 0; g2 < 8; g2++) v += smf[bb][g2][k];
            a[k] = v;
        }
        const float Sp = a[0], Spg = a[1];
        const float pec = a[2], pmc = a[3], pjc = a[4];
        const float Np = a[5], Ng = a[6];
        const float gec = a[7], gmc = a[8], gjc = a[9];
        const float Ie = a[10], Im = a[11], Ij = a[12];
        const float medP = a[13] + Np;   // + d>=1 term for every on-pixel
        const float medG = a[14] + Ng;
        const float Sg = Ng;

        float dice = (2.0f * Spg + 1.0f) / (Sp + Sg + 1.0f);
        float eiou = (Ie + 1.0f) / (pec + gec - Ie + 1.0f);
        float miou = (Im + 1.0f) / (pmc + gmc - Im + 1.0f);
        float jiou = (Ij + 1.0f) / (pjc + gjc - Ij + 1.0f);
        float total3 = gec + gjc + gmc + 1.0f;
        float sloss = 1.0f - ((gec / total3) * eiou + (gjc / total3) * jiou
                              + (gmc / total3) * miou);
        float p2g = medP / (Np + 1.0f);
        float g2p = medG / (Ng + 1.0f);
        float med = ((p2g + g2p) * 0.5f) / 10.0f;

        float sd = dice, ss = sloss, sme = med;
#pragma unroll
        for (int off = 16; off > 0; off >>= 1) {
            sd  += __shfl_down_sync(0xFFFFFFFFu, sd, off);
            ss  += __shfl_down_sync(0xFFFFFFFFu, ss, off);
            sme += __shfl_down_sync(0xFFFFFFFFu, sme, off);
        }
        if (tid == 0) {
            float dice_loss = 1.0f - sd / 32.0f;
            float structural_loss = ss / 32.0f;
            float medial_loss = sme / 32.0f;
            float avg = (dice_loss + structural_loss + medial_loss) / 3.0f;
            out[0] = dice_loss / (dice_loss + 1.0f) * avg
                   + structural_loss / (structural_loss + 1.0f) * avg
                   + medial_loss / (medial_loss + 1.0f) * avg;
            g_ticket = 0u;  // reset for next graph replay
        }
    }
}

extern "C" void kernel_launch(void* const* d_in, const int* in_sizes, int n_in,
                              void* d_out, int out_size) {
    const float* pred = (const float*)d_in[0];
    const float* gt   = (const float*)d_in[1];
    float* out = (float*)d_out;

    k1_pixel<<<NB * 16, 256>>>(pred, gt);   // 512 blocks: (batch, half, 64-row chunk)
    k2_dilate<<<K2BLK, 256>>>(out);         // 296 blocks: one warp item per warp
}